// round 6
// baseline (speedup 1.0000x reference)
#include <cuda_runtime.h>
#include <cuda_bf16.h>
#include <cuda_fp16.h>
#include <math.h>
#include <stdint.h>

#define F_DIM 256
#define MAX_N 100000
#define BUCKET_CAP 128

// ---------------- static device scratch (allocation-guard-safe) -------------
__device__ unsigned long long g_bucket[(size_t)MAX_N * BUCKET_CAP]; // 102.4 MB
__device__ int                g_cnt[MAX_N];
__device__ __half             g_xh[(size_t)MAX_N * F_DIM];          // x fp16 (51.2 MB)
__device__ __nv_bfloat16      g_wt_hi[F_DIM * F_DIM];               // W^T hi
__device__ __nv_bfloat16      g_wt_lo[F_DIM * F_DIM];               // W^T lo

__device__ __forceinline__ float scal(const void* p) {
    int i = *(const int*)p;
    if (i > 0 && i < 1000000) return (float)i;
    return *(const float*)p;
}
__device__ __forceinline__ uint32_t smem_u32(const void* p) {
    uint32_t a;
    asm("{ .reg .u64 t; cvta.to.shared.u64 t, %1; cvt.u32.u64 %0, t; }" : "=r"(a) : "l"(p));
    return a;
}

#define LDSM4(r0, r1, r2, r3, addr) \
    asm volatile("ldmatrix.sync.aligned.m8n8.x4.shared.b16 {%0,%1,%2,%3}, [%4];" \
                 : "=r"(r0), "=r"(r1), "=r"(r2), "=r"(r3) : "r"(addr))
#define MMA16816(d, a0, a1, a2, a3, b0, b1) \
    asm volatile("mma.sync.aligned.m16n8k16.row.col.f32.bf16.bf16.f32 " \
                 "{%0,%1,%2,%3}, {%4,%5,%6,%7}, {%8,%9}, {%0,%1,%2,%3};" \
                 : "+f"((d)[0]), "+f"((d)[1]), "+f"((d)[2]), "+f"((d)[3]) \
                 : "r"(a0), "r"(a1), "r"(a2), "r"(a3), "r"(b0), "r"(b1))
#define CPA16(sa, gp) \
    asm volatile("cp.async.cg.shared.global [%0], [%1], 16;" \
                 :: "r"(sa), "l"(gp) : "memory")
#define CPA_COMMIT() asm volatile("cp.async.commit_group;" ::: "memory")
#define CPA_WAIT0()  asm volatile("cp.async.wait_group 0;" ::: "memory")

__device__ __forceinline__ unsigned pack_bf2(float x, float y) {
    unsigned a = (unsigned)__bfloat16_as_ushort(__float2bfloat16_rn(x));
    unsigned b = (unsigned)__bfloat16_as_ushort(__float2bfloat16_rn(y));
    return a | (b << 16);
}

// ---------------------------------------------------------------------------
// Prep kernels
// ---------------------------------------------------------------------------
__global__ void convert_x_kernel(const float* __restrict__ x, int n8) {
    int i = blockIdx.x * blockDim.x + threadIdx.x;
    if (i >= n8) return;
    float4 a = __ldg(reinterpret_cast<const float4*>(x) + i * 2);
    float4 b = __ldg(reinterpret_cast<const float4*>(x) + i * 2 + 1);
    __half2* o = reinterpret_cast<__half2*>(g_xh) + i * 4;
    o[0] = __floats2half2_rn(a.x, a.y);
    o[1] = __floats2half2_rn(a.z, a.w);
    o[2] = __floats2half2_rn(b.x, b.y);
    o[3] = __floats2half2_rn(b.z, b.w);
}

__global__ void zero_cnt_kernel(int n4) {
    int i = blockIdx.x * blockDim.x + threadIdx.x;
    if (i < n4) reinterpret_cast<int4*>(g_cnt)[i] = make_int4(0, 0, 0, 0);
}

__global__ void fill_kernel(const int* __restrict__ rows, const int* __restrict__ cols,
                            const float* __restrict__ vals, int E) {
    int e = blockIdx.x * blockDim.x + threadIdx.x;
    if (e >= E) return;
    int r = rows[e];
    int pos = atomicAdd(&g_cnt[r], 1);
    if (pos < BUCKET_CAP) {
        unsigned long long pv = (unsigned)cols[e] |
                                ((unsigned long long)__float_as_uint(vals[e]) << 32);
        g_bucket[(size_t)r * BUCKET_CAP + pos] = pv;
    }
}

__global__ void wt_split_kernel(const float* __restrict__ W) {
    int k = blockIdx.x;
    int n = threadIdx.x;
    float w = __ldg(W + k * F_DIM + n);
    __nv_bfloat16 hi = __float2bfloat16_rn(w);
    float rem = w - __bfloat162float(hi);
    g_wt_hi[n * F_DIM + k] = hi;
    g_wt_lo[n * F_DIM + k] = __float2bfloat16_rn(rem);
}

// ---------------------------------------------------------------------------
// FUSED kernel: per CTA (128 rows x full 256 cols):
//   Phase 1: spmm gather (fp16 x) + blend h0 -> support bf16 hi/lo in SMEM
//   Phase 2: 3-product bf16 MMA against W^T hi/lo (B streamed per 64-K chunk)
//   Epilogue: direct fragment stores; support re-read from SMEM
// ---------------------------------------------------------------------------
#define A_STRIDE 528                       // 256*2 + 16 bytes
#define A_HI_OFF 0
#define A_LO_OFF (128 * A_STRIDE)          // 67584
#define B_HI_OFF (2 * 128 * A_STRIDE)      // 135168
#define B_LO_OFF (B_HI_OFF + 256 * 144)    // 172032
#define SMEM_SZ  (B_LO_OFF + 256 * 144)    // 208896

__global__ __launch_bounds__(512, 1)
void fused_kernel(const float* __restrict__ h0,
                  const float* __restrict__ p_lamda,
                  const float* __restrict__ p_alpha,
                  const float* __restrict__ p_l,
                  float* __restrict__ out,
                  int Nrows) {
    extern __shared__ char smem[];
    uint32_t sb = smem_u32(smem);
    int tid = threadIdx.x, wid = tid >> 5, lane = tid & 31;
    int warp_m = wid & 3, warp_n = wid >> 2;

    float alpha = scal(p_alpha);
    float lamda = scal(p_lamda);
    float lf    = scal(p_l);
    float theta = logf(lamda / lf + 1.0f);
    float oma   = 1.0f - alpha;
    float omt   = 1.0f - theta;

    int rowBase = blockIdx.x * 128;

    // B cp.async mapping (per chunk): 8x 16B per thread
    int bN = tid >> 1, bHalf = tid & 1;
    const char* bHiG = reinterpret_cast<const char*>(g_wt_hi) + (size_t)bN * 512 + bHalf * 64;
    const char* bLoG = reinterpret_cast<const char*>(g_wt_lo) + (size_t)bN * 512 + bHalf * 64;
    uint32_t bS = sb + bN * 144 + bHalf * 64;

#define LOAD_B(ch) do {                                                        \
    int kb = (ch) * 128;                                                       \
    _Pragma("unroll")                                                          \
    for (int i = 0; i < 4; i++) {                                              \
        CPA16(bS + B_HI_OFF + i * 16, bHiG + kb + i * 16);                     \
        CPA16(bS + B_LO_OFF + i * 16, bLoG + kb + i * 16);                     \
    }                                                                          \
    CPA_COMMIT();                                                              \
} while (0)

    // prefetch B chunk 0 while phase 1 runs
    LOAD_B(0);

    // ---------------- Phase 1: spmm + blend -> SMEM support hi/lo ----------
    for (int i = 0; i < 8; i++) {
        int rowL = wid * 8 + i;
        int rowG = rowBase + rowL;
        float acc[8];
#pragma unroll
        for (int j = 0; j < 8; j++) acc[j] = 0.f;

        if (rowG < Nrows) {
            int deg = g_cnt[rowG];
            if (deg > BUCKET_CAP) deg = BUCKET_CAP;
            const unsigned long long* bk = g_bucket + (size_t)rowG * BUCKET_CAP;
#pragma unroll 8
            for (int e = 0; e < deg; e++) {
                unsigned long long pv = __ldg(bk + e);
                int   c = (int)(unsigned)(pv & 0xffffffffull);
                float v = __uint_as_float((unsigned)(pv >> 32));
                uint4 xv = __ldg(reinterpret_cast<const uint4*>(g_xh + (size_t)c * F_DIM) + lane);
                const __half2* hp = reinterpret_cast<const __half2*>(&xv);
#pragma unroll
                for (int j = 0; j < 4; j++) {
                    float2 f = __half22float2(hp[j]);
                    acc[j * 2]     += v * f.x;
                    acc[j * 2 + 1] += v * f.y;
                }
            }
            size_t off = (size_t)rowG * F_DIM + lane * 8;
            float4 h0a = __ldg(reinterpret_cast<const float4*>(h0 + off));
            float4 h0b = __ldg(reinterpret_cast<const float4*>(h0 + off + 4));
            float h0v[8] = {h0a.x, h0a.y, h0a.z, h0a.w, h0b.x, h0b.y, h0b.z, h0b.w};
#pragma unroll
            for (int j = 0; j < 8; j++)
                acc[j] = oma * acc[j] + alpha * h0v[j];
        }
        unsigned hiw[4], low[4];
#pragma unroll
        for (int j = 0; j < 4; j++) {
            float s0 = acc[j * 2], s1 = acc[j * 2 + 1];
            float r0 = s0 - __bfloat162float(__float2bfloat16_rn(s0));
            float r1 = s1 - __bfloat162float(__float2bfloat16_rn(s1));
            hiw[j] = pack_bf2(s0, s1);
            low[j] = pack_bf2(r0, r1);
        }
        uint32_t ao = (uint32_t)(rowL * A_STRIDE + lane * 16);
        *reinterpret_cast<uint4*>(smem + A_HI_OFF + ao) = make_uint4(hiw[0], hiw[1], hiw[2], hiw[3]);
        *reinterpret_cast<uint4*>(smem + A_LO_OFF + ao) = make_uint4(low[0], low[1], low[2], low[3]);
    }
    __syncthreads();

    // ---------------- Phase 2: MMA over 4 K-chunks -------------------------
    float acc[2][8][4];
#pragma unroll
    for (int i = 0; i < 2; i++)
#pragma unroll
        for (int j = 0; j < 8; j++)
#pragma unroll
            for (int q = 0; q < 4; q++) acc[i][j][q] = 0.f;

    for (int ch = 0; ch < 4; ch++) {
        CPA_WAIT0();
        __syncthreads();

#pragma unroll
        for (int ks = 0; ks < 4; ks++) {
            int kbB = ks * 32;
            int kbA = ch * 128 + ks * 32;
            uint32_t aH[8], aL[8];
            {
                uint32_t arow = (lane & 7) + ((lane >> 3) & 1) * 8;
                uint32_t abyt = kbA + ((lane >> 4) & 1) * 16;
#pragma unroll
                for (int mt = 0; mt < 2; mt++) {
                    uint32_t m0 = warp_m * 32 + mt * 16;
                    uint32_t ad = sb + (m0 + arow) * A_STRIDE + abyt;
                    LDSM4(aH[mt*4], aH[mt*4+1], aH[mt*4+2], aH[mt*4+3], ad + A_HI_OFF);
                    LDSM4(aL[mt*4], aL[mt*4+1], aL[mt*4+2], aL[mt*4+3], ad + A_LO_OFF);
                }
            }
            uint32_t brow = (lane & 7) + ((lane >> 4) & 1) * 8;
            uint32_t bbyt = kbB + ((lane >> 3) & 1) * 16;
#pragma unroll
            for (int nt2 = 0; nt2 < 4; nt2++) {
                uint32_t n0 = warp_n * 64 + nt2 * 16;
                uint32_t bd = sb + (n0 + brow) * 144 + bbyt;
                uint32_t bH[4], bL[4];
                LDSM4(bH[0], bH[1], bH[2], bH[3], bd + B_HI_OFF);
                LDSM4(bL[0], bL[1], bL[2], bL[3], bd + B_LO_OFF);
#pragma unroll
                for (int mt = 0; mt < 2; mt++) {
#pragma unroll
                    for (int ntl = 0; ntl < 2; ntl++) {
                        float* d = acc[mt][nt2 * 2 + ntl];
                        MMA16816(d, aH[mt*4], aH[mt*4+1], aH[mt*4+2], aH[mt*4+3],
                                 bH[ntl*2], bH[ntl*2+1]);
                        MMA16816(d, aH[mt*4], aH[mt*4+1], aH[mt*4+2], aH[mt*4+3],
                                 bL[ntl*2], bL[ntl*2+1]);
                        MMA16816(d, aL[mt*4], aL[mt*4+1], aL[mt*4+2], aL[mt*4+3],
                                 bH[ntl*2], bH[ntl*2+1]);
                    }
                }
            }
        }
        __syncthreads();
        if (ch < 3) LOAD_B(ch + 1);
    }

    // ---------------- Epilogue: direct fragment stores ---------------------
    {
        int colQ = (lane & 3) * 2;
        int rQ   = lane >> 2;
#pragma unroll
        for (int mt = 0; mt < 2; mt++) {
            int rowL0 = warp_m * 32 + mt * 16 + rQ;
#pragma unroll
            for (int nt = 0; nt < 8; nt++) {
                int col = warp_n * 64 + (nt >> 1) * 16 + (nt & 1) * 8 + colQ;
#pragma unroll
                for (int half = 0; half < 2; half++) {
                    int rowL = rowL0 + half * 8;
                    int rowG = rowBase + rowL;
                    if (rowG >= Nrows) continue;
                    float d0 = acc[mt][nt][half * 2];
                    float d1 = acc[mt][nt][half * 2 + 1];
                    uint32_t so = (uint32_t)(rowL * A_STRIDE + col * 2);
                    unsigned hw = *reinterpret_cast<const unsigned*>(smem + A_HI_OFF + so);
                    unsigned lw = *reinterpret_cast<const unsigned*>(smem + A_LO_OFF + so);
                    float2 sh = __bfloat1622float2(*reinterpret_cast<const __nv_bfloat162*>(&hw));
                    float2 sl = __bfloat1622float2(*reinterpret_cast<const __nv_bfloat162*>(&lw));
                    float2 o;
                    o.x = theta * d0 + omt * (sh.x + sl.x);
                    o.y = theta * d1 + omt * (sh.y + sl.y);
                    *reinterpret_cast<float2*>(out + (size_t)rowG * F_DIM + col) = o;
                }
            }
        }
    }
}

// ---------------------------------------------------------------------------
// kernel_launch
// ---------------------------------------------------------------------------
extern "C" void kernel_launch(void* const* d_in, const int* in_sizes, int n_in,
                              void* d_out, int out_size) {
    const float* x       = (const float*)d_in[0];
    const int*   rows    = (const int*)d_in[1];
    const int*   cols    = (const int*)d_in[2];
    const float* vals    = (const float*)d_in[3];
    const float* h0      = (const float*)d_in[4];
    const float* W       = (const float*)d_in[5];
    const float* p_lamda = (const float*)d_in[6];
    const float* p_alpha = (const float*)d_in[7];
    const float* p_l     = (const float*)d_in[8];
    float* out = (float*)d_out;

    int N = in_sizes[0] / F_DIM;
    int E = in_sizes[2];

    cudaFuncSetAttribute(fused_kernel, cudaFuncAttributeMaxDynamicSharedMemorySize, SMEM_SZ);

    int n8 = N * (F_DIM / 8);
    convert_x_kernel<<<(n8 + 255) / 256, 256>>>(x, n8);
    zero_cnt_kernel<<<(N / 4 + 255) / 256, 256>>>((N + 3) / 4);
    fill_kernel<<<(E + 255) / 256, 256>>>(rows, cols, vals, E);
    wt_split_kernel<<<F_DIM, F_DIM>>>(W);

    int grid = (N + 127) / 128;
    fused_kernel<<<grid, 512, SMEM_SZ>>>(h0, p_lamda, p_alpha, p_l, out, N);
}

// round 7
// speedup vs baseline: 1.5538x; 1.5538x over previous
#include <cuda_runtime.h>
#include <cuda_bf16.h>
#include <cuda_fp16.h>
#include <math.h>
#include <stdint.h>

#define F_DIM 256
#define MAX_N 100000
#define BUCKET_CAP 128

// ---------------- static device scratch (allocation-guard-safe) -------------
__device__ unsigned long long g_bucket[(size_t)MAX_N * BUCKET_CAP]; // 102.4 MB
__device__ int                g_cnt[MAX_N];
__device__ __half             g_xh[(size_t)MAX_N * F_DIM];          // x fp16 (51.2 MB)
__device__ __half             g_sh[(size_t)MAX_N * F_DIM];          // support fp16 (51.2 MB)
__device__ __half             g_wt[F_DIM * F_DIM];                  // W^T fp16

__device__ __forceinline__ float scal(const void* p) {
    int i = *(const int*)p;
    if (i > 0 && i < 1000000) return (float)i;
    return *(const float*)p;
}
__device__ __forceinline__ uint32_t smem_u32(const void* p) {
    uint32_t a;
    asm("{ .reg .u64 t; cvta.to.shared.u64 t, %1; cvt.u32.u64 %0, t; }" : "=r"(a) : "l"(p));
    return a;
}

#define LDSM4(r0, r1, r2, r3, addr) \
    asm volatile("ldmatrix.sync.aligned.m8n8.x4.shared.b16 {%0,%1,%2,%3}, [%4];" \
                 : "=r"(r0), "=r"(r1), "=r"(r2), "=r"(r3) : "r"(addr))
#define MMA16816F16(d, a0, a1, a2, a3, b0, b1) \
    asm volatile("mma.sync.aligned.m16n8k16.row.col.f32.f16.f16.f32 " \
                 "{%0,%1,%2,%3}, {%4,%5,%6,%7}, {%8,%9}, {%0,%1,%2,%3};" \
                 : "+f"((d)[0]), "+f"((d)[1]), "+f"((d)[2]), "+f"((d)[3]) \
                 : "r"(a0), "r"(a1), "r"(a2), "r"(a3), "r"(b0), "r"(b1))
#define CPA16(sa, gp, sz) \
    asm volatile("cp.async.cg.shared.global [%0], [%1], 16, %2;" \
                 :: "r"(sa), "l"(gp), "r"(sz) : "memory")
#define CPA_COMMIT() asm volatile("cp.async.commit_group;" ::: "memory")
#define CPA_WAIT(n)  asm volatile("cp.async.wait_group %0;" :: "n"(n) : "memory")

// ---------------------------------------------------------------------------
// Prep kernels
// ---------------------------------------------------------------------------
__global__ void convert_x_kernel(const float* __restrict__ x, int n8) {
    int i = blockIdx.x * blockDim.x + threadIdx.x;
    if (i >= n8) return;
    float4 a = __ldg(reinterpret_cast<const float4*>(x) + i * 2);
    float4 b = __ldg(reinterpret_cast<const float4*>(x) + i * 2 + 1);
    __half2* o = reinterpret_cast<__half2*>(g_xh) + i * 4;
    o[0] = __floats2half2_rn(a.x, a.y);
    o[1] = __floats2half2_rn(a.z, a.w);
    o[2] = __floats2half2_rn(b.x, b.y);
    o[3] = __floats2half2_rn(b.z, b.w);
}

__global__ void zero_cnt_kernel(int n4) {
    int i = blockIdx.x * blockDim.x + threadIdx.x;
    if (i < n4) reinterpret_cast<int4*>(g_cnt)[i] = make_int4(0, 0, 0, 0);
}

__global__ void fill_kernel(const int* __restrict__ rows, const int* __restrict__ cols,
                            const float* __restrict__ vals, int E) {
    int e = blockIdx.x * blockDim.x + threadIdx.x;
    if (e >= E) return;
    int r = rows[e];
    int pos = atomicAdd(&g_cnt[r], 1);
    if (pos < BUCKET_CAP) {
        unsigned long long pv = (unsigned)cols[e] |
                                ((unsigned long long)__float_as_uint(vals[e]) << 32);
        g_bucket[(size_t)r * BUCKET_CAP + pos] = pv;
    }
}

__global__ void wt_fp16_kernel(const float* __restrict__ W) {
    int k = blockIdx.x;
    int n = threadIdx.x;
    g_wt[n * F_DIM + k] = __float2half_rn(__ldg(W + k * F_DIM + n));
}

// ---------------------------------------------------------------------------
// SpMM + blend: support = (1-alpha)*(A@x) + alpha*h0, stored fp16.
// One warp per row; fp16 gather; fp32 accumulate.
// ---------------------------------------------------------------------------
__global__ __launch_bounds__(256)
void spmm_kernel(const float* __restrict__ h0,
                 const float* __restrict__ p_alpha, int N) {
    int r = blockIdx.x * 8 + (threadIdx.x >> 5);
    if (r >= N) return;
    int lane = threadIdx.x & 31;
    float alpha = scal(p_alpha);
    float oma   = 1.0f - alpha;

    int deg = g_cnt[r];
    if (deg > BUCKET_CAP) deg = BUCKET_CAP;
    const unsigned long long* bk = g_bucket + (size_t)r * BUCKET_CAP;

    float acc[8];
#pragma unroll
    for (int j = 0; j < 8; j++) acc[j] = 0.f;

#pragma unroll 4
    for (int e = 0; e < deg; e++) {
        unsigned long long pv = __ldg(bk + e);
        int   c = (int)(unsigned)(pv & 0xffffffffull);
        float v = __uint_as_float((unsigned)(pv >> 32));
        uint4 xv = __ldg(reinterpret_cast<const uint4*>(g_xh + (size_t)c * F_DIM) + lane);
        const __half2* hp = reinterpret_cast<const __half2*>(&xv);
#pragma unroll
        for (int j = 0; j < 4; j++) {
            float2 f = __half22float2(hp[j]);
            acc[j * 2]     += v * f.x;
            acc[j * 2 + 1] += v * f.y;
        }
    }

    size_t off = (size_t)r * F_DIM + lane * 8;
    float4 h0a = __ldg(reinterpret_cast<const float4*>(h0 + off));
    float4 h0b = __ldg(reinterpret_cast<const float4*>(h0 + off + 4));
    float h0v[8] = {h0a.x, h0a.y, h0a.z, h0a.w, h0b.x, h0b.y, h0b.z, h0b.w};
    unsigned w[4];
#pragma unroll
    for (int j = 0; j < 4; j++) {
        float s0 = oma * acc[j * 2]     + alpha * h0v[j * 2];
        float s1 = oma * acc[j * 2 + 1] + alpha * h0v[j * 2 + 1];
        __half2 h2 = __floats2half2_rn(s0, s1);
        w[j] = *reinterpret_cast<const unsigned*>(&h2);
    }
    *reinterpret_cast<uint4*>(g_sh + off) = make_uint4(w[0], w[1], w[2], w[3]);
}

// ---------------------------------------------------------------------------
// GEMM via mma.sync m16n8k16 fp16 (single product). Double-buffered cp.async.
// CTA: 128 rows x 256 cols, K chunked 4x64. 512 threads / 16 warps.
// Epilogue: direct fragment stores, support re-read from fp16 plane.
// ---------------------------------------------------------------------------
#define A_OFF    0
#define B_OFF    18432                     // 128 rows * 144B
#define STAGE_SZ 55296                     // + 256 n * 144B
#define SMEM_SZ  (2 * STAGE_SZ)            // 110592

__global__ __launch_bounds__(512, 1)
void gemm_mma_kernel(const float* __restrict__ p_lamda,
                     const float* __restrict__ p_l,
                     float* __restrict__ out,
                     int Nrows) {
    extern __shared__ char smem[];
    uint32_t sb = smem_u32(smem);
    int tid = threadIdx.x, wid = tid >> 5, lane = tid & 31;
    int warp_m = wid & 3, warp_n = wid >> 2;

    float lamda = scal(p_lamda);
    float lf    = scal(p_l);
    float theta = logf(lamda / lf + 1.0f);
    float omt   = 1.0f - theta;

    int rowBase = blockIdx.x * 128;

    // A cp.async mapping: 4 threads per row, 2x16B each (row = 128B/chunk)
    int aRow = tid >> 2, aQ = tid & 3;
    int aRowG = rowBase + aRow;
    unsigned aSz = (aRowG < Nrows) ? 16u : 0u;
    const char* aG = reinterpret_cast<const char*>(g_sh) +
                     (size_t)(aRowG < Nrows ? aRowG : 0) * 512 + aQ * 16;
    uint32_t aS = sb + A_OFF + aRow * 144 + aQ * 16;
    // B cp.async mapping: 2 threads per n-row, 4x16B each
    int bN = tid >> 1, bHalf = tid & 1;
    const char* bG = reinterpret_cast<const char*>(g_wt) + (size_t)bN * 512 + bHalf * 64;
    uint32_t bS = sb + B_OFF + bN * 144 + bHalf * 64;

#define LOAD_STAGE(ch, buf) do {                                               \
    uint32_t stg = (buf) * STAGE_SZ;                                           \
    int kb = (ch) * 128;                                                       \
    CPA16(aS + stg,      aG + kb,      aSz);                                   \
    CPA16(aS + stg + 64, aG + kb + 64, aSz);                                   \
    _Pragma("unroll")                                                          \
    for (int i = 0; i < 4; i++)                                                \
        CPA16(bS + stg + i * 16, bG + kb + i * 16, 16u);                       \
    CPA_COMMIT();                                                              \
} while (0)

    float acc[2][8][4];
#pragma unroll
    for (int i = 0; i < 2; i++)
#pragma unroll
        for (int j = 0; j < 8; j++)
#pragma unroll
            for (int q = 0; q < 4; q++) acc[i][j][q] = 0.f;

    LOAD_STAGE(0, 0);

    for (int ch = 0; ch < 4; ch++) {
        if (ch < 3) LOAD_STAGE(ch + 1, (ch + 1) & 1);
        if (ch < 3) { CPA_WAIT(1); } else { CPA_WAIT(0); }
        __syncthreads();

        uint32_t stg = sb + (ch & 1) * STAGE_SZ;
#pragma unroll
        for (int ks = 0; ks < 4; ks++) {
            int kb = ks * 32;
            uint32_t aF[8];
            {
                uint32_t arow = (lane & 7) + ((lane >> 3) & 1) * 8;
                uint32_t abyt = kb + ((lane >> 4) & 1) * 16;
#pragma unroll
                for (int mt = 0; mt < 2; mt++) {
                    uint32_t m0 = warp_m * 32 + mt * 16;
                    LDSM4(aF[mt*4], aF[mt*4+1], aF[mt*4+2], aF[mt*4+3],
                          stg + A_OFF + (m0 + arow) * 144 + abyt);
                }
            }
            uint32_t brow = (lane & 7) + ((lane >> 4) & 1) * 8;
            uint32_t bbyt = kb + ((lane >> 3) & 1) * 16;
#pragma unroll
            for (int nt2 = 0; nt2 < 4; nt2++) {
                uint32_t n0 = warp_n * 64 + nt2 * 16;
                uint32_t bF[4];
                LDSM4(bF[0], bF[1], bF[2], bF[3],
                      stg + B_OFF + (n0 + brow) * 144 + bbyt);
#pragma unroll
                for (int mt = 0; mt < 2; mt++) {
#pragma unroll
                    for (int ntl = 0; ntl < 2; ntl++) {
                        MMA16816F16(acc[mt][nt2 * 2 + ntl],
                                    aF[mt*4], aF[mt*4+1], aF[mt*4+2], aF[mt*4+3],
                                    bF[ntl*2], bF[ntl*2+1]);
                    }
                }
            }
        }
        __syncthreads();
    }

    // ---- epilogue: direct fragment stores; support from fp16 plane --------
    {
        int colQ = (lane & 3) * 2;
        int rQ   = lane >> 2;
#pragma unroll
        for (int mt = 0; mt < 2; mt++) {
            int rowL0 = warp_m * 32 + mt * 16 + rQ;
#pragma unroll
            for (int nt = 0; nt < 8; nt++) {
                int col = warp_n * 64 + (nt >> 1) * 16 + (nt & 1) * 8 + colQ;
#pragma unroll
                for (int half = 0; half < 2; half++) {
                    int rowG = rowBase + rowL0 + half * 8;
                    if (rowG >= Nrows) continue;
                    float d0 = acc[mt][nt][half * 2];
                    float d1 = acc[mt][nt][half * 2 + 1];
                    size_t off = (size_t)rowG * F_DIM + col;
                    __half2 sh2 = *reinterpret_cast<const __half2*>(g_sh + off);
                    float2 s = __half22float2(sh2);
                    float2 o;
                    o.x = theta * d0 + omt * s.x;
                    o.y = theta * d1 + omt * s.y;
                    *reinterpret_cast<float2*>(out + off) = o;
                }
            }
        }
    }
}

// ---------------------------------------------------------------------------
// kernel_launch
// ---------------------------------------------------------------------------
extern "C" void kernel_launch(void* const* d_in, const int* in_sizes, int n_in,
                              void* d_out, int out_size) {
    const float* x       = (const float*)d_in[0];
    const int*   rows    = (const int*)d_in[1];
    const int*   cols    = (const int*)d_in[2];
    const float* vals    = (const float*)d_in[3];
    const float* h0      = (const float*)d_in[4];
    const float* W       = (const float*)d_in[5];
    const float* p_lamda = (const float*)d_in[6];
    const float* p_alpha = (const float*)d_in[7];
    const float* p_l     = (const float*)d_in[8];
    float* out = (float*)d_out;

    int N = in_sizes[0] / F_DIM;
    int E = in_sizes[2];

    cudaFuncSetAttribute(gemm_mma_kernel, cudaFuncAttributeMaxDynamicSharedMemorySize, SMEM_SZ);

    int n8 = N * (F_DIM / 8);
    convert_x_kernel<<<(n8 + 255) / 256, 256>>>(x, n8);
    zero_cnt_kernel<<<(N / 4 + 255) / 256, 256>>>((N + 3) / 4);
    fill_kernel<<<(E + 255) / 256, 256>>>(rows, cols, vals, E);
    wt_fp16_kernel<<<F_DIM, F_DIM>>>(W);
    spmm_kernel<<<(N + 7) / 8, 256>>>(h0, p_alpha, N);

    int grid = (N + 127) / 128;
    gemm_mma_kernel<<<grid, 512, SMEM_SZ>>>(p_lamda, p_l, out, N);
}

// round 8
// speedup vs baseline: 1.6504x; 1.0622x over previous
#include <cuda_runtime.h>
#include <cuda_bf16.h>
#include <cuda_fp16.h>
#include <math.h>
#include <stdint.h>

#define F_DIM 256
#define MAX_N 100000
#define BUCKET_CAP 128

// ---------------- static device scratch (allocation-guard-safe) -------------
__device__ unsigned long long g_bucket[(size_t)MAX_N * BUCKET_CAP]; // 102.4 MB
__device__ int                g_cnt[MAX_N];
__device__ __half             g_xh[(size_t)MAX_N * F_DIM];          // x fp16 (51.2 MB)
__device__ __half             g_sh[(size_t)MAX_N * F_DIM];          // support fp16 (51.2 MB)
__device__ __half             g_wt[F_DIM * F_DIM];                  // W^T fp16

__device__ __forceinline__ float scal(const void* p) {
    int i = *(const int*)p;
    if (i > 0 && i < 1000000) return (float)i;
    return *(const float*)p;
}
__device__ __forceinline__ uint32_t smem_u32(const void* p) {
    uint32_t a;
    asm("{ .reg .u64 t; cvta.to.shared.u64 t, %1; cvt.u32.u64 %0, t; }" : "=r"(a) : "l"(p));
    return a;
}

#define LDSM4(r0, r1, r2, r3, addr) \
    asm volatile("ldmatrix.sync.aligned.m8n8.x4.shared.b16 {%0,%1,%2,%3}, [%4];" \
                 : "=r"(r0), "=r"(r1), "=r"(r2), "=r"(r3) : "r"(addr))
#define MMA16816F16(d, a0, a1, a2, a3, b0, b1) \
    asm volatile("mma.sync.aligned.m16n8k16.row.col.f32.f16.f16.f32 " \
                 "{%0,%1,%2,%3}, {%4,%5,%6,%7}, {%8,%9}, {%0,%1,%2,%3};" \
                 : "+f"((d)[0]), "+f"((d)[1]), "+f"((d)[2]), "+f"((d)[3]) \
                 : "r"(a0), "r"(a1), "r"(a2), "r"(a3), "r"(b0), "r"(b1))
#define CPA16(sa, gp, sz) \
    asm volatile("cp.async.cg.shared.global [%0], [%1], 16, %2;" \
                 :: "r"(sa), "l"(gp), "r"(sz) : "memory")
#define CPA_COMMIT() asm volatile("cp.async.commit_group;" ::: "memory")
#define CPA_WAIT(n)  asm volatile("cp.async.wait_group %0;" :: "n"(n) : "memory")

// ---------------------------------------------------------------------------
// Prep kernels
// ---------------------------------------------------------------------------
__global__ void convert_x_kernel(const float* __restrict__ x, int n8, int nCnt4) {
    int i = blockIdx.x * blockDim.x + threadIdx.x;
    if (i < nCnt4) reinterpret_cast<int4*>(g_cnt)[i] = make_int4(0, 0, 0, 0);
    if (i >= n8) return;
    float4 a = __ldg(reinterpret_cast<const float4*>(x) + i * 2);
    float4 b = __ldg(reinterpret_cast<const float4*>(x) + i * 2 + 1);
    __half2* o = reinterpret_cast<__half2*>(g_xh) + i * 4;
    o[0] = __floats2half2_rn(a.x, a.y);
    o[1] = __floats2half2_rn(a.z, a.w);
    o[2] = __floats2half2_rn(b.x, b.y);
    o[3] = __floats2half2_rn(b.z, b.w);
}

__global__ void fill_kernel(const int* __restrict__ rows, const int* __restrict__ cols,
                            const float* __restrict__ vals, int E) {
    int e0 = (blockIdx.x * blockDim.x + threadIdx.x) * 2;
    if (e0 >= E) return;
    int n = (e0 + 1 < E) ? 2 : 1;
    int2   r2 = *reinterpret_cast<const int2*>(rows + e0);
    int2   c2 = *reinterpret_cast<const int2*>(cols + e0);
    float2 v2 = *reinterpret_cast<const float2*>(vals + e0);
#pragma unroll
    for (int j = 0; j < 2; j++) {
        if (j >= n) break;
        int r = j ? r2.y : r2.x;
        int c = j ? c2.y : c2.x;
        float v = j ? v2.y : v2.x;
        int pos = atomicAdd(&g_cnt[r], 1);
        if (pos < BUCKET_CAP) {
            unsigned long long pv = (unsigned)c |
                                    ((unsigned long long)__float_as_uint(v) << 32);
            g_bucket[(size_t)r * BUCKET_CAP + pos] = pv;
        }
    }
}

__global__ void wt_fp16_kernel(const float* __restrict__ W) {
    int k = blockIdx.x;
    int n = threadIdx.x;
    g_wt[n * F_DIM + k] = __float2half_rn(__ldg(W + k * F_DIM + n));
}

// ---------------------------------------------------------------------------
// SpMM + blend: support = (1-alpha)*(A@x) + alpha*h0, stored fp16.
// ---------------------------------------------------------------------------
__global__ __launch_bounds__(256)
void spmm_kernel(const float* __restrict__ h0,
                 const float* __restrict__ p_alpha, int N) {
    int r = blockIdx.x * 8 + (threadIdx.x >> 5);
    if (r >= N) return;
    int lane = threadIdx.x & 31;
    float alpha = scal(p_alpha);
    float oma   = 1.0f - alpha;

    int deg = g_cnt[r];
    if (deg > BUCKET_CAP) deg = BUCKET_CAP;
    const unsigned long long* bk = g_bucket + (size_t)r * BUCKET_CAP;

    float acc[8];
#pragma unroll
    for (int j = 0; j < 8; j++) acc[j] = 0.f;

#pragma unroll 8
    for (int e = 0; e < deg; e++) {
        unsigned long long pv = __ldg(bk + e);
        int   c = (int)(unsigned)(pv & 0xffffffffull);
        float v = __uint_as_float((unsigned)(pv >> 32));
        uint4 xv = __ldg(reinterpret_cast<const uint4*>(g_xh + (size_t)c * F_DIM) + lane);
        const __half2* hp = reinterpret_cast<const __half2*>(&xv);
#pragma unroll
        for (int j = 0; j < 4; j++) {
            float2 f = __half22float2(hp[j]);
            acc[j * 2]     += v * f.x;
            acc[j * 2 + 1] += v * f.y;
        }
    }

    size_t off = (size_t)r * F_DIM + lane * 8;
    float4 h0a = __ldg(reinterpret_cast<const float4*>(h0 + off));
    float4 h0b = __ldg(reinterpret_cast<const float4*>(h0 + off + 4));
    float h0v[8] = {h0a.x, h0a.y, h0a.z, h0a.w, h0b.x, h0b.y, h0b.z, h0b.w};
    unsigned w[4];
#pragma unroll
    for (int j = 0; j < 4; j++) {
        float s0 = oma * acc[j * 2]     + alpha * h0v[j * 2];
        float s1 = oma * acc[j * 2 + 1] + alpha * h0v[j * 2 + 1];
        __half2 h2 = __floats2half2_rn(s0, s1);
        w[j] = *reinterpret_cast<const unsigned*>(&h2);
    }
    *reinterpret_cast<uint4*>(g_sh + off) = make_uint4(w[0], w[1], w[2], w[3]);
}

// ---------------------------------------------------------------------------
// GEMM fp16 mma.sync. CTA 128x128, 256 threads, 2 CTAs/SM.
// K chunked 4x64, double-buffered cp.async.
// ---------------------------------------------------------------------------
#define A_OFF    0
#define B_OFF    18432                     // 128 rows * 144B
#define STAGE_SZ 36864
#define SMEM_SZ  (2 * STAGE_SZ)            // 73728

__global__ __launch_bounds__(256, 2)
void gemm_mma_kernel(const float* __restrict__ p_lamda,
                     const float* __restrict__ p_l,
                     float* __restrict__ out,
                     int Nrows) {
    extern __shared__ char smem[];
    uint32_t sb = smem_u32(smem);
    int tid = threadIdx.x, wid = tid >> 5, lane = tid & 31;
    int warp_m = wid & 3, warp_n = wid >> 2;

    float lamda = scal(p_lamda);
    float lf    = scal(p_l);
    float theta = logf(lamda / lf + 1.0f);
    float omt   = 1.0f - theta;

    int rowBase = blockIdx.y * 128;
    int colBase = blockIdx.x * 128;

    // A cp.async: 2 threads/row, 4x16B each (64B halves of the 128B k-chunk row)
    int aRow = tid >> 1, aHalf = tid & 1;
    int aRowG = rowBase + aRow;
    unsigned aSz = (aRowG < Nrows) ? 16u : 0u;
    const char* aG = reinterpret_cast<const char*>(g_sh) +
                     (size_t)(aRowG < Nrows ? aRowG : 0) * 512 + aHalf * 64;
    uint32_t aS = sb + A_OFF + aRow * 144 + aHalf * 64;
    // B cp.async: 2 threads/n-row, 4x16B each
    const char* bG = reinterpret_cast<const char*>(g_wt) +
                     (size_t)(colBase + aRow) * 512 + aHalf * 64;
    uint32_t bS = sb + B_OFF + aRow * 144 + aHalf * 64;

#define LOAD_STAGE(ch, buf) do {                                               \
    uint32_t stg = (buf) * STAGE_SZ;                                           \
    int kb = (ch) * 128;                                                       \
    _Pragma("unroll")                                                          \
    for (int i = 0; i < 4; i++) {                                              \
        CPA16(aS + stg + i * 16, aG + kb + i * 16, aSz);                       \
        CPA16(bS + stg + i * 16, bG + kb + i * 16, 16u);                       \
    }                                                                          \
    CPA_COMMIT();                                                              \
} while (0)

    float acc[2][8][4];
#pragma unroll
    for (int i = 0; i < 2; i++)
#pragma unroll
        for (int j = 0; j < 8; j++)
#pragma unroll
            for (int q = 0; q < 4; q++) acc[i][j][q] = 0.f;

    LOAD_STAGE(0, 0);

    for (int ch = 0; ch < 4; ch++) {
        if (ch < 3) LOAD_STAGE(ch + 1, (ch + 1) & 1);
        if (ch < 3) { CPA_WAIT(1); } else { CPA_WAIT(0); }
        __syncthreads();

        uint32_t stg = sb + (ch & 1) * STAGE_SZ;
#pragma unroll
        for (int ks = 0; ks < 4; ks++) {
            int kb = ks * 32;
            uint32_t aF[8];
            {
                uint32_t arow = (lane & 7) + ((lane >> 3) & 1) * 8;
                uint32_t abyt = kb + ((lane >> 4) & 1) * 16;
#pragma unroll
                for (int mt = 0; mt < 2; mt++) {
                    uint32_t m0 = warp_m * 32 + mt * 16;
                    LDSM4(aF[mt*4], aF[mt*4+1], aF[mt*4+2], aF[mt*4+3],
                          stg + A_OFF + (m0 + arow) * 144 + abyt);
                }
            }
            uint32_t brow = (lane & 7) + ((lane >> 4) & 1) * 8;
            uint32_t bbyt = kb + ((lane >> 3) & 1) * 16;
#pragma unroll
            for (int nt2 = 0; nt2 < 4; nt2++) {
                uint32_t n0 = warp_n * 64 + nt2 * 16;
                uint32_t bF[4];
                LDSM4(bF[0], bF[1], bF[2], bF[3],
                      stg + B_OFF + (n0 + brow) * 144 + bbyt);
#pragma unroll
                for (int mt = 0; mt < 2; mt++) {
#pragma unroll
                    for (int ntl = 0; ntl < 2; ntl++) {
                        MMA16816F16(acc[mt][nt2 * 2 + ntl],
                                    aF[mt*4], aF[mt*4+1], aF[mt*4+2], aF[mt*4+3],
                                    bF[ntl*2], bF[ntl*2+1]);
                    }
                }
            }
        }
        __syncthreads();
    }

    // ---- epilogue: direct fragment stores; support from fp16 plane --------
    {
        int colQ = (lane & 3) * 2;
        int rQ   = lane >> 2;
#pragma unroll
        for (int mt = 0; mt < 2; mt++) {
            int rowL0 = warp_m * 32 + mt * 16 + rQ;
#pragma unroll
            for (int nt = 0; nt < 8; nt++) {
                int col = colBase + warp_n * 64 + (nt >> 1) * 16 + (nt & 1) * 8 + colQ;
#pragma unroll
                for (int half = 0; half < 2; half++) {
                    int rowG = rowBase + rowL0 + half * 8;
                    if (rowG >= Nrows) continue;
                    float d0 = acc[mt][nt][half * 2];
                    float d1 = acc[mt][nt][half * 2 + 1];
                    size_t off = (size_t)rowG * F_DIM + col;
                    __half2 sh2 = *reinterpret_cast<const __half2*>(g_sh + off);
                    float2 s = __half22float2(sh2);
                    float2 o;
                    o.x = theta * d0 + omt * s.x;
                    o.y = theta * d1 + omt * s.y;
                    *reinterpret_cast<float2*>(out + off) = o;
                }
            }
        }
    }
}

// ---------------------------------------------------------------------------
// kernel_launch
// ---------------------------------------------------------------------------
extern "C" void kernel_launch(void* const* d_in, const int* in_sizes, int n_in,
                              void* d_out, int out_size) {
    const float* x       = (const float*)d_in[0];
    const int*   rows    = (const int*)d_in[1];
    const int*   cols    = (const int*)d_in[2];
    const float* vals    = (const float*)d_in[3];
    const float* h0      = (const float*)d_in[4];
    const float* W       = (const float*)d_in[5];
    const float* p_lamda = (const float*)d_in[6];
    const float* p_alpha = (const float*)d_in[7];
    const float* p_l     = (const float*)d_in[8];
    float* out = (float*)d_out;

    int N = in_sizes[0] / F_DIM;
    int E = in_sizes[2];

    cudaFuncSetAttribute(gemm_mma_kernel, cudaFuncAttributeMaxDynamicSharedMemorySize, SMEM_SZ);

    int n8 = N * (F_DIM / 8);
    convert_x_kernel<<<(n8 + 255) / 256, 256>>>(x, n8, (N + 3) / 4);
    fill_kernel<<<(E / 2 + 255) / 256, 256>>>(rows, cols, vals, E);
    wt_fp16_kernel<<<F_DIM, F_DIM>>>(W);
    spmm_kernel<<<(N + 7) / 8, 256>>>(h0, p_alpha, N);

    dim3 g(2, (N + 127) / 128);
    gemm_mma_kernel<<<g, 256, SMEM_SZ>>>(p_lamda, p_l, out, N);
}